// round 9
// baseline (speedup 1.0000x reference)
#include <cuda_runtime.h>
#include <cuda_bf16.h>

// img : (1, 64, 64, 1024) float32, NHWC
// rois: (1, 512, 4) int32  -> (x, y, w, h)
// out : (1, 512, 7, 7, 1024) float32
#define POOL   7
#define NROIS  512
#define IMG_W  64

// ---- packed f32x2 helpers (sm_103a) ----
__device__ __forceinline__ unsigned long long pk(float v) {
    unsigned long long r;
    asm("mov.b64 %0, {%1, %1};" : "=l"(r) : "f"(v));
    return r;
}
__device__ __forceinline__ unsigned long long mul2(unsigned long long a, unsigned long long b) {
    unsigned long long r;
    asm("mul.rn.f32x2 %0, %1, %2;" : "=l"(r) : "l"(a), "l"(b));
    return r;
}
__device__ __forceinline__ unsigned long long fma2(unsigned long long a, unsigned long long b,
                                                   unsigned long long c) {
    unsigned long long r;
    asm("fma.rn.f32x2 %0, %1, %2, %3;" : "=l"(r) : "l"(a), "l"(b), "l"(c));
    return r;
}

// 16B img load, non-coherent, keep resident in L1 (reused across px/py).
__device__ __forceinline__ ulonglong2 ldg_el(const ulonglong2* p) {
    ulonglong2 v;
    asm("ld.global.nc.L1::evict_last.v2.b64 {%0, %1}, [%2];"
        : "=l"(v.x), "=l"(v.y) : "l"(p));
    return v;
}
// 16B streaming store (output never re-read).
__device__ __forceinline__ void stg_cs(ulonglong2* p, ulonglong2 v) {
    asm volatile("st.global.cs.v2.b64 [%0], {%1, %2};"
                 :: "l"(p), "l"(v.x), "l"(v.y) : "memory");
}

__device__ __forceinline__ ulonglong2 blend2(ulonglong2 v00, ulonglong2 v01,
                                             ulonglong2 v10, ulonglong2 v11,
                                             float fx, float fy) {
    const float w11 = fx * fy;
    const float w01 = fx - w11;          // fx*(1-fy)
    const float w10 = fy - w11;          // (1-fx)*fy
    const float w00 = 1.0f - fx - w10;   // (1-fx)*(1-fy)
    const unsigned long long W00 = pk(w00), W01 = pk(w01),
                             W10 = pk(w10), W11 = pk(w11);
    ulonglong2 o;
    o.x = fma2(v11.x, W11, fma2(v10.x, W10, fma2(v01.x, W01, mul2(v00.x, W00))));
    o.y = fma2(v11.y, W11, fma2(v10.y, W10, fma2(v01.y, W01, mul2(v00.y, W00))));
    return o;
}

// One CTA per ROI: 49 cells, 256 threads, 1 float4 lane each. All 512 CTAs
// are resident at once (single wave, zero CTA churn). Outer loop over py
// (row bases / fy amortized over 7 px cells); inner px loop is depth-1
// software-pipelined: 8 independent 16B loads in flight per thread.
__global__ __launch_bounds__(256, 4)
void roi_pool_kernel(const float* __restrict__ img,
                     const int*   __restrict__ rois,
                     float*       __restrict__ out)
{
    const int roi = blockIdx.x;

    const int4 r = __ldg(((const int4*)rois) + roi);   // x, y, w, h

    const float stepx = (float)r.z / (float)POOL;
    const float stepy = (float)r.w / (float)POOL;
    const int   wm1 = r.z - 1;
    const int   hm1 = r.w - 1;

    const int c = threadIdx.x;            // 0..255 float4 lane
    const ulonglong2* ibase = (const ulonglong2*)img;
    // Base of the ROI origin row (includes x-origin and lane).
    const unsigned obase0 = (unsigned)(r.y * IMG_W + r.x) * 256u + c;

    ulonglong2* optr = (ulonglong2*)out + ((size_t)roi * (POOL * POOL)) * 256 + c;

    #pragma unroll
    for (int py = 0; py < POOL; ++py) {
        // Per-row y work (match reference fp32 arithmetic exactly)
        const float sy = (float)py * stepy;
        const int   y0 = (int)sy;
        const float fy = sy - (float)y0;
        const int   y1 = min(y0 + 1, hm1);

        const unsigned row0 = obase0 + (unsigned)(y0 * IMG_W) * 256u;
        const unsigned row1 = obase0 + (unsigned)(y1 * IMG_W) * 256u;

        // ---- px = 0 prologue (sx = 0, x0 = 0, fx = 0) ----
        float fxc = 0.0f;
        const unsigned x1u0 = (unsigned)min(1, wm1) * 256u;
        ulonglong2 a00 = ldg_el(ibase + row0);
        ulonglong2 a01 = ldg_el(ibase + row0 + x1u0);
        ulonglong2 a10 = ldg_el(ibase + row1);
        ulonglong2 a11 = ldg_el(ibase + row1 + x1u0);

        #pragma unroll
        for (int px = 1; px < POOL; ++px) {
            const float sx  = (float)px * stepx;
            const int   x0  = (int)sx;
            const float fxn = sx - (float)x0;
            const unsigned u0 = (unsigned)x0 * 256u;
            const unsigned u1 = (unsigned)min(x0 + 1, wm1) * 256u;

            // prefetch next cell before consuming current registers
            const ulonglong2 b00 = ldg_el(ibase + row0 + u0);
            const ulonglong2 b01 = ldg_el(ibase + row0 + u1);
            const ulonglong2 b10 = ldg_el(ibase + row1 + u0);
            const ulonglong2 b11 = ldg_el(ibase + row1 + u1);

            stg_cs(optr, blend2(a00, a01, a10, a11, fxc, fy));
            optr += 256;

            a00 = b00; a01 = b01; a10 = b10; a11 = b11;
            fxc = fxn;
        }

        // ---- px = 6 epilogue ----
        stg_cs(optr, blend2(a00, a01, a10, a11, fxc, fy));
        optr += 256;
    }
}

extern "C" void kernel_launch(void* const* d_in, const int* in_sizes, int n_in,
                              void* d_out, int out_size)
{
    const float* img  = (const float*)d_in[0];
    const int*   rois = (const int*)d_in[1];
    float*       out  = (float*)d_out;

    roi_pool_kernel<<<NROIS, 256>>>(img, rois, out);   // 512 CTAs, one wave
}

// round 10
// speedup vs baseline: 1.1504x; 1.1504x over previous
#include <cuda_runtime.h>
#include <cuda_bf16.h>

// img : (1, 64, 64, 1024) float32, NHWC
// rois: (1, 512, 4) int32  -> (x, y, w, h)
// out : (1, 512, 7, 7, 1024) float32
#define POOL   7
#define NROIS  512
#define IMG_W  64

// ---- packed f32x2 helpers (sm_103a) ----
__device__ __forceinline__ unsigned long long pk(float v) {
    unsigned long long r;
    asm("mov.b64 %0, {%1, %1};" : "=l"(r) : "f"(v));
    return r;
}
__device__ __forceinline__ unsigned long long mul2(unsigned long long a, unsigned long long b) {
    unsigned long long r;
    asm("mul.rn.f32x2 %0, %1, %2;" : "=l"(r) : "l"(a), "l"(b));
    return r;
}
__device__ __forceinline__ unsigned long long fma2(unsigned long long a, unsigned long long b,
                                                   unsigned long long c) {
    unsigned long long r;
    asm("fma.rn.f32x2 %0, %1, %2, %3;" : "=l"(r) : "l"(a), "l"(b), "l"(c));
    return r;
}

// 16B streaming store (output never re-read) — don't pollute L1.
__device__ __forceinline__ void stg_cs(ulonglong2* p, ulonglong2 v) {
    asm volatile("st.global.cs.v2.b64 [%0], {%1, %2};"
                 :: "l"(p), "l"(v.x), "l"(v.y) : "memory");
}

__device__ __forceinline__ ulonglong2 blend2(ulonglong2 v00, ulonglong2 v01,
                                             ulonglong2 v10, ulonglong2 v11,
                                             float fx, float fy) {
    const float w11 = fx * fy;
    const float w01 = fx - w11;          // fx*(1-fy)
    const float w10 = fy - w11;          // (1-fx)*fy
    const float w00 = 1.0f - fx - w10;   // (1-fx)*(1-fy)
    const unsigned long long W00 = pk(w00), W01 = pk(w01),
                             W10 = pk(w10), W11 = pk(w11);
    ulonglong2 o;
    o.x = fma2(v11.x, W11, fma2(v10.x, W10, fma2(v01.x, W01, mul2(v00.x, W00))));
    o.y = fma2(v11.y, W11, fma2(v10.y, W10, fma2(v01.y, W01, mul2(v00.y, W00))));
    return o;
}

// One CTA per (roi, py) output row: 7 px cells, 256 threads, 1 float4 lane
// each. Depth-1 software pipeline over px (up to 8 independent 16B loads in
// flight per thread), bilinear blend in packed f32x2, plain L1-cached img
// loads (default policy measured fastest), streaming stores.
__global__ __launch_bounds__(256)
void roi_pool_kernel(const float* __restrict__ img,
                     const int*   __restrict__ rois,
                     float*       __restrict__ out)
{
    const int bid = blockIdx.x;           // roi*7 + py
    const int roi = bid / POOL;
    const int py  = bid - roi * POOL;

    const int4 r = __ldg(((const int4*)rois) + roi);   // x, y, w, h

    // Loop-invariant y-axis work (match reference fp32 arithmetic exactly)
    const float stepx = (float)r.z / (float)POOL;
    const float sy = (float)py * ((float)r.w / (float)POOL);
    const int   y0 = (int)sy;
    const float fy = sy - (float)y0;
    const int   y1 = min(y0 + 1, r.w - 1);
    const int   wm1 = r.z - 1;

    const int c = threadIdx.x;            // 0..255 float4 lane
    const ulonglong2* ibase = (const ulonglong2*)img;
    const unsigned row0 = (unsigned)((r.y + y0) * IMG_W + r.x) * 256u + c;
    const unsigned row1 = (unsigned)((r.y + y1) * IMG_W + r.x) * 256u + c;

    ulonglong2* optr = (ulonglong2*)out + ((size_t)bid * POOL) * 256 + c;

    // ---- prologue: px = 0 (sx = 0, x0 = 0, fx = 0) ----
    float fxc = 0.0f;
    {
        const unsigned x1u = (unsigned)min(1, wm1) * 256u;
        ulonglong2 a00 = __ldg(ibase + row0);
        ulonglong2 a01 = __ldg(ibase + row0 + x1u);
        ulonglong2 a10 = __ldg(ibase + row1);
        ulonglong2 a11 = __ldg(ibase + row1 + x1u);

        #pragma unroll
        for (int px = 1; px < POOL; ++px) {
            const float sx  = (float)px * stepx;
            const int   x0  = (int)sx;
            const float fxn = sx - (float)x0;
            const unsigned u0 = (unsigned)x0 * 256u;
            const unsigned u1 = (unsigned)min(x0 + 1, wm1) * 256u;

            // prefetch next cell's four pixels before consuming current regs
            const ulonglong2 b00 = __ldg(ibase + row0 + u0);
            const ulonglong2 b01 = __ldg(ibase + row0 + u1);
            const ulonglong2 b10 = __ldg(ibase + row1 + u0);
            const ulonglong2 b11 = __ldg(ibase + row1 + u1);

            stg_cs(optr, blend2(a00, a01, a10, a11, fxc, fy));
            optr += 256;

            a00 = b00; a01 = b01; a10 = b10; a11 = b11;
            fxc = fxn;
        }

        // ---- epilogue: px = 6 ----
        stg_cs(optr, blend2(a00, a01, a10, a11, fxc, fy));
    }
}

extern "C" void kernel_launch(void* const* d_in, const int* in_sizes, int n_in,
                              void* d_out, int out_size)
{
    const float* img  = (const float*)d_in[0];
    const int*   rois = (const int*)d_in[1];
    float*       out  = (float*)d_out;

    const int grid = NROIS * POOL;        // 3584 CTAs, one per (roi, py)
    roi_pool_kernel<<<grid, 256>>>(img, rois, out);
}